// round 2
// baseline (speedup 1.0000x reference)
#include <cuda_runtime.h>

// Problem constants (B=2, N=2048, C=1024, H=16, hd=64)
#define BDIM   2
#define NSEQ   2048
#define CDIM   1024
#define MDIM   (BDIM * NSEQ)   // 4096 rows
#define C3     (3 * CDIM)      // 3072
#define H4DIM  (4 * CDIM)      // 4096
#define NHEAD  16
#define HD     64

// ---------------------------------------------------------------------------
// Scratch (device globals: allocation-free). Referenced device-side only.
// ---------------------------------------------------------------------------
__device__ float g_hln[MDIM * CDIM];          // 16 MB  (LN output, reused)
__device__ float g_qkv[MDIM * C3];            // 48 MB
__device__ float g_x2 [MDIM * CDIM];          // 16 MB  (x + attn residual)
__device__ float g_ff1[MDIM * H4DIM];         // 64 MB

// ---------------------------------------------------------------------------
// LayerNorm body: one block per row of 1024, 256 threads, float4 per thread
// ---------------------------------------------------------------------------
__device__ __forceinline__ void ln_body(
    const float* __restrict__ in, const float* __restrict__ gam,
    const float* __restrict__ bet, float* __restrict__ out)
{
    int row = blockIdx.x;
    int t   = threadIdx.x;
    const float4* rin = reinterpret_cast<const float4*>(in + (size_t)row * CDIM);
    float4 v = rin[t];
    float s  = v.x + v.y + v.z + v.w;
    float sq = v.x * v.x + v.y * v.y + v.z * v.z + v.w * v.w;
    #pragma unroll
    for (int o = 16; o; o >>= 1) {
        s  += __shfl_xor_sync(0xffffffffu, s,  o);
        sq += __shfl_xor_sync(0xffffffffu, sq, o);
    }
    __shared__ float ss[8], ssq[8];
    int w = t >> 5, l = t & 31;
    if (l == 0) { ss[w] = s; ssq[w] = sq; }
    __syncthreads();
    if (w == 0) {
        s  = (l < 8) ? ss[l]  : 0.0f;
        sq = (l < 8) ? ssq[l] : 0.0f;
        #pragma unroll
        for (int o = 4; o; o >>= 1) {
            s  += __shfl_xor_sync(0xffffffffu, s,  o);
            sq += __shfl_xor_sync(0xffffffffu, sq, o);
        }
        if (l == 0) { ss[0] = s; ssq[0] = sq; }
    }
    __syncthreads();
    float mu  = ss[0] * (1.0f / CDIM);
    float var = ssq[0] * (1.0f / CDIM) - mu * mu;
    float rs  = rsqrtf(var + 1e-5f);
    float4 gv = reinterpret_cast<const float4*>(gam)[t];
    float4 bv = reinterpret_cast<const float4*>(bet)[t];
    float4 o4;
    o4.x = (v.x - mu) * rs * gv.x + bv.x;
    o4.y = (v.y - mu) * rs * gv.y + bv.y;
    o4.z = (v.z - mu) * rs * gv.z + bv.z;
    o4.w = (v.w - mu) * rs * gv.w + bv.w;
    reinterpret_cast<float4*>(out + (size_t)row * CDIM)[t] = o4;
}

__global__ __launch_bounds__(256) void ln1_kernel(
    const float* __restrict__ x, const float* __restrict__ gam,
    const float* __restrict__ bet)
{
    ln_body(x, gam, bet, g_hln);
}

__global__ __launch_bounds__(256) void ln2_kernel(
    const float* __restrict__ gam, const float* __restrict__ bet)
{
    ln_body(g_x2, gam, bet, g_hln);
}

// ---------------------------------------------------------------------------
// fp32 SGEMM body: C[M,N] = epilogue(A[M,K] @ B[K,N] + bias)
// Tile 128x128x8, 256 threads, 8x8 per thread, register-prefetched loads.
// MODE 0: +bias, MODE 1: relu(+bias), MODE 2: +bias + residual
// All dims multiples of tile sizes (no bounds checks).
// ---------------------------------------------------------------------------
template <int MODE>
__device__ __forceinline__ void sgemm_body(
    const float* __restrict__ A, const float* __restrict__ Bw,
    const float* __restrict__ bias, const float* __restrict__ res,
    float* __restrict__ C, int M, int N, int K)
{
    __shared__ float As[8][128];
    __shared__ float Bs[8][128];

    int tid = threadIdx.x;
    int bm = blockIdx.y * 128;
    int bn = blockIdx.x * 128;

    int arow = tid >> 1;            // 0..127
    int acol = (tid & 1) * 4;       // 0 or 4
    int brow = tid >> 5;            // 0..7
    int bcol = (tid & 31) * 4;      // 0..124

    const float* Ap = A  + (size_t)(bm + arow) * K + acol;
    const float* Bp = Bw + (size_t)brow * N + bn + bcol;

    float acc[8][8];
    #pragma unroll
    for (int i = 0; i < 8; ++i)
        #pragma unroll
        for (int j = 0; j < 8; ++j) acc[i][j] = 0.0f;

    int tx = tid & 15, ty = tid >> 4;

    float4 av = *reinterpret_cast<const float4*>(Ap);
    float4 bv = *reinterpret_cast<const float4*>(Bp);

    int ktiles = K >> 3;
    for (int t = 0; t < ktiles; ++t) {
        As[acol + 0][arow] = av.x;
        As[acol + 1][arow] = av.y;
        As[acol + 2][arow] = av.z;
        As[acol + 3][arow] = av.w;
        *reinterpret_cast<float4*>(&Bs[brow][bcol]) = bv;
        __syncthreads();

        if (t + 1 < ktiles) {
            Ap += 8;
            Bp += (size_t)8 * N;
            av = *reinterpret_cast<const float4*>(Ap);
            bv = *reinterpret_cast<const float4*>(Bp);
        }

        #pragma unroll
        for (int k = 0; k < 8; ++k) {
            float4 a0 = *reinterpret_cast<float4*>(&As[k][ty * 8]);
            float4 a1 = *reinterpret_cast<float4*>(&As[k][ty * 8 + 4]);
            float4 b0 = *reinterpret_cast<float4*>(&Bs[k][tx * 8]);
            float4 b1 = *reinterpret_cast<float4*>(&Bs[k][tx * 8 + 4]);
            float ar[8] = {a0.x, a0.y, a0.z, a0.w, a1.x, a1.y, a1.z, a1.w};
            float br[8] = {b0.x, b0.y, b0.z, b0.w, b1.x, b1.y, b1.z, b1.w};
            #pragma unroll
            for (int i = 0; i < 8; ++i)
                #pragma unroll
                for (int j = 0; j < 8; ++j)
                    acc[i][j] = fmaf(ar[i], br[j], acc[i][j]);
        }
        __syncthreads();
    }

    #pragma unroll
    for (int i = 0; i < 8; ++i) {
        int gm = bm + ty * 8 + i;
        #pragma unroll
        for (int j = 0; j < 8; ++j) {
            int gn = bn + tx * 8 + j;
            float v = acc[i][j] + bias[gn];
            if (MODE == 1) v = fmaxf(v, 0.0f);
            if (MODE == 2) v += res[(size_t)gm * N + gn];
            C[(size_t)gm * N + gn] = v;
        }
    }
}

// GEMM wrappers binding the device-global scratch (no host symbol lookups)
__global__ __launch_bounds__(256) void qkv_gemm_kernel(
    const float* __restrict__ w, const float* __restrict__ b)
{
    sgemm_body<0>(g_hln, w, b, nullptr, g_qkv, MDIM, C3, CDIM);
}

__global__ __launch_bounds__(256) void mlp1_gemm_kernel(
    const float* __restrict__ w, const float* __restrict__ b)
{
    sgemm_body<1>(g_hln, w, b, nullptr, g_ff1, MDIM, H4DIM, CDIM);
}

__global__ __launch_bounds__(256) void mlp2_gemm_kernel(
    const float* __restrict__ w, const float* __restrict__ b,
    float* __restrict__ out)
{
    sgemm_body<2>(g_ff1, w, b, g_x2, out, MDIM, CDIM, H4DIM);
}

// ---------------------------------------------------------------------------
// Flash attention, fp32, static smem (<48KB).
// Per block: 64 query rows of one (b,h); loop over 64 key tiles of 32.
// Writes result with source-faithful interleaved-head reshape + residual:
//   x2[b, h*128 + n/16, (n%16)*64 + d] = x[...] + softmax(QK^T/32) @ V
// ---------------------------------------------------------------------------
#define KT 32       // key tile
#define SP 33       // score pitch (33: kills bank conflicts on P reads)

__global__ __launch_bounds__(256) void attn_kernel(const float* __restrict__ xin)
{
    __shared__ float Qt[64 * 64];      // [d][m] transposed Q tile
    __shared__ float Kt[64 * KT];      // [d][j] transposed K tile
    __shared__ float Vs[KT * 64];      // [j][d] V tile
    __shared__ float Ss[64 * SP];      // [m][j] scores / probs
    __shared__ float row_m[64], row_l[64], row_a[64];

    const float SCALE = 1.0f / 32.0f;  // 1/sqrt(C) per source

    int tid  = threadIdx.x;
    int tx   = tid & 15, ty = tid >> 4;
    int lane = tid & 31, warp = tid >> 5;

    int bh = blockIdx.y;
    int b  = bh >> 4;          // / NHEAD
    int h  = bh & 15;
    int qbase = blockIdx.x * 64;

    const float* qkv_b = g_qkv + (size_t)b * NSEQ * C3;

    // Q load mapping: 64 rows, 4 thread-groups of 16 floats
    int tm  = tid >> 2;        // 0..63
    int tdg = (tid & 3) << 4;  // 0,16,32,48
    {
        const float* qp = qkv_b + (size_t)(qbase + tm) * C3 + h * HD + tdg;
        #pragma unroll
        for (int i = 0; i < 4; ++i) {
            float4 v = *reinterpret_cast<const float4*>(qp + 4 * i);
            int d = tdg + 4 * i;
            Qt[(d + 0) * 64 + tm] = v.x;
            Qt[(d + 1) * 64 + tm] = v.y;
            Qt[(d + 2) * 64 + tm] = v.z;
            Qt[(d + 3) * 64 + tm] = v.w;
        }
    }
    if (tid < 64) { row_m[tid] = -1e30f; row_l[tid] = 0.0f; }

    float o_acc[4][4];
    #pragma unroll
    for (int i = 0; i < 4; ++i)
        #pragma unroll
        for (int j = 0; j < 4; ++j) o_acc[i][j] = 0.0f;

    // K/V load mapping: 32 rows, 8 thread-groups of 8 floats
    int km  = tid >> 3;        // 0..31
    int kdg = (tid & 7) << 3;  // 0..56

    for (int kt = 0; kt < NSEQ / KT; ++kt) {
        int kbase = kt * KT;
        {
            const float* kp = qkv_b + (size_t)(kbase + km) * C3 + CDIM + h * HD + kdg;
            #pragma unroll
            for (int i = 0; i < 2; ++i) {
                float4 v = *reinterpret_cast<const float4*>(kp + 4 * i);
                int d = kdg + 4 * i;
                Kt[(d + 0) * KT + km] = v.x;
                Kt[(d + 1) * KT + km] = v.y;
                Kt[(d + 2) * KT + km] = v.z;
                Kt[(d + 3) * KT + km] = v.w;
            }
            const float* vp = qkv_b + (size_t)(kbase + km) * C3 + 2 * CDIM + h * HD + kdg;
            #pragma unroll
            for (int i = 0; i < 2; ++i)
                *reinterpret_cast<float4*>(&Vs[km * 64 + kdg + 4 * i]) =
                    *reinterpret_cast<const float4*>(vp + 4 * i);
        }
        __syncthreads();

        // S = Q @ K^T  (64x32x64); thread computes 4 rows x 2 cols
        float s_acc[4][2];
        #pragma unroll
        for (int i = 0; i < 4; ++i) { s_acc[i][0] = 0.0f; s_acc[i][1] = 0.0f; }
        for (int d = 0; d < 64; ++d) {
            float4 qa = *reinterpret_cast<float4*>(&Qt[d * 64 + ty * 4]);
            float2 kb = *reinterpret_cast<float2*>(&Kt[d * KT + tx * 2]);
            float aq[4] = {qa.x, qa.y, qa.z, qa.w};
            #pragma unroll
            for (int i = 0; i < 4; ++i) {
                s_acc[i][0] = fmaf(aq[i], kb.x, s_acc[i][0]);
                s_acc[i][1] = fmaf(aq[i], kb.y, s_acc[i][1]);
            }
        }
        #pragma unroll
        for (int i = 0; i < 4; ++i) {
            Ss[(ty * 4 + i) * SP + tx * 2 + 0] = s_acc[i][0] * SCALE;
            Ss[(ty * 4 + i) * SP + tx * 2 + 1] = s_acc[i][1] * SCALE;
        }
        __syncthreads();

        // Online softmax: warp w handles rows w*8 .. w*8+7, one lane per col
        #pragma unroll
        for (int r = 0; r < 8; ++r) {
            int m = warp * 8 + r;
            float s1 = Ss[m * SP + lane];
            float mx = s1;
            #pragma unroll
            for (int o = 16; o; o >>= 1)
                mx = fmaxf(mx, __shfl_xor_sync(0xffffffffu, mx, o));
            float mold = row_m[m];
            float mnew = fmaxf(mold, mx);
            float p1 = __expf(s1 - mnew);
            float ps = p1;
            #pragma unroll
            for (int o = 16; o; o >>= 1)
                ps += __shfl_xor_sync(0xffffffffu, ps, o);
            if (lane == 0) {
                float alpha = __expf(mold - mnew);
                row_a[m] = alpha;
                row_l[m] = row_l[m] * alpha + ps;
                row_m[m] = mnew;
            }
            Ss[m * SP + lane] = p1;
        }
        __syncthreads();

        // O = O*alpha + P @ V   (thread: 4 rows x 4 d-cols)
        float al[4];
        #pragma unroll
        for (int i = 0; i < 4; ++i) al[i] = row_a[ty * 4 + i];
        #pragma unroll
        for (int i = 0; i < 4; ++i)
            #pragma unroll
            for (int j = 0; j < 4; ++j) o_acc[i][j] *= al[i];
        #pragma unroll 4
        for (int j = 0; j < KT; ++j) {
            float4 vb = *reinterpret_cast<float4*>(&Vs[j * 64 + tx * 4]);
            float pv[4];
            #pragma unroll
            for (int i = 0; i < 4; ++i) pv[i] = Ss[(ty * 4 + i) * SP + j];
            #pragma unroll
            for (int i = 0; i < 4; ++i) {
                o_acc[i][0] = fmaf(pv[i], vb.x, o_acc[i][0]);
                o_acc[i][1] = fmaf(pv[i], vb.y, o_acc[i][1]);
                o_acc[i][2] = fmaf(pv[i], vb.z, o_acc[i][2]);
                o_acc[i][3] = fmaf(pv[i], vb.w, o_acc[i][3]);
            }
        }
        __syncthreads();
    }

    // Epilogue: normalize, interleaved-head scatter, residual add -> g_x2
    #pragma unroll
    for (int i = 0; i < 4; ++i) {
        int m = ty * 4 + i;
        int n = qbase + m;
        float invl = 1.0f / row_l[m];
        int np = h * 128 + (n >> 4);
        int cbase = (n & 15) << 6;
        #pragma unroll
        for (int j = 0; j < 4; ++j) {
            int d = tx * 4 + j;
            size_t oi = ((size_t)b * NSEQ + np) * CDIM + cbase + d;
            g_x2[oi] = xin[oi] + o_acc[i][j] * invl;
        }
    }
}

// ---------------------------------------------------------------------------
// Launch: kernel launches ONLY (graph-capture-minimal)
// ---------------------------------------------------------------------------
extern "C" void kernel_launch(void* const* d_in, const int* in_sizes, int n_in,
                              void* d_out, int out_size)
{
    const float* x     = (const float*)d_in[0];
    const float* qkv_w = (const float*)d_in[1];
    const float* qkv_b = (const float*)d_in[2];
    const float* w1    = (const float*)d_in[3];
    const float* b1    = (const float*)d_in[4];
    const float* w2    = (const float*)d_in[5];
    const float* b2    = (const float*)d_in[6];
    const float* ln1_g = (const float*)d_in[7];
    const float* ln1_b = (const float*)d_in[8];
    const float* ln2_g = (const float*)d_in[9];
    const float* ln2_b = (const float*)d_in[10];
    float* out = (float*)d_out;

    // 1. LN1: x -> g_hln
    ln1_kernel<<<MDIM, 256>>>(x, ln1_g, ln1_b);
    // 2. QKV projection: g_hln @ qkv_w -> g_qkv
    qkv_gemm_kernel<<<dim3(C3 / 128, MDIM / 128), 256>>>(qkv_w, qkv_b);
    // 3. Attention (+ interleaved reshape + residual): -> g_x2
    attn_kernel<<<dim3(NSEQ / 64, BDIM * NHEAD), 256>>>(x);
    // 4. LN2: g_x2 -> g_hln
    ln2_kernel<<<MDIM, 256>>>(ln2_g, ln2_b);
    // 5. MLP up + relu: g_hln @ w1 -> g_ff1
    mlp1_gemm_kernel<<<dim3(H4DIM / 128, MDIM / 128), 256>>>(w1, b1);
    // 6. MLP down + bias + residual: g_ff1 @ w2 + g_x2 -> out
    mlp2_gemm_kernel<<<dim3(CDIM / 128, MDIM / 128), 256>>>(w2, b2, out);
}

// round 6
// speedup vs baseline: 1.3216x; 1.3216x over previous
#include <cuda_runtime.h>
#include <cuda_bf16.h>
#include <cstdint>

// Problem constants (B=2, N=2048, C=1024, H=16, hd=64)
#define BDIM   2
#define NSEQ   2048
#define CDIM   1024
#define MDIM   (BDIM * NSEQ)   // 4096 rows
#define C3     (3 * CDIM)      // 3072
#define H4DIM  (4 * CDIM)      // 4096
#define NHEAD  16
#define HD     64

// ---------------------------------------------------------------------------
// Scratch (device globals: allocation-free)
// ---------------------------------------------------------------------------
__device__ float g_qkv[MDIM * C3];                 // 48 MB  QKV projections (fp32)
__device__ float g_x2 [MDIM * CDIM];               // 16 MB  x + attn residual
__device__ __nv_bfloat16 g_ah1[MDIM * CDIM];       // LN out hi
__device__ __nv_bfloat16 g_al1[MDIM * CDIM];       // LN out lo
__device__ __nv_bfloat16 g_ah2[MDIM * H4DIM];      // relu out hi
__device__ __nv_bfloat16 g_al2[MDIM * H4DIM];      // relu out lo
__device__ __nv_bfloat16 g_wqh[C3 * CDIM];         // qkv_w^T hi  [3072,1024]
__device__ __nv_bfloat16 g_wql[C3 * CDIM];
__device__ __nv_bfloat16 g_w1h[H4DIM * CDIM];      // w1^T hi     [4096,1024]
__device__ __nv_bfloat16 g_w1l[H4DIM * CDIM];
__device__ __nv_bfloat16 g_w2h[CDIM * H4DIM];      // w2^T hi     [1024,4096]
__device__ __nv_bfloat16 g_w2l[CDIM * H4DIM];

// ---------------------------------------------------------------------------
// Helpers
// ---------------------------------------------------------------------------
__device__ __forceinline__ uint32_t smem_u32(const void* p) {
    uint32_t a;
    asm("{ .reg .u64 t; cvta.to.shared.u64 t, %1; cvt.u32.u64 %0, t; }"
        : "=r"(a) : "l"(p));
    return a;
}

__device__ __forceinline__ void ldmatrix_x4(
    uint32_t& r0, uint32_t& r1, uint32_t& r2, uint32_t& r3, uint32_t addr)
{
    asm volatile("ldmatrix.sync.aligned.m8n8.x4.shared.b16 {%0,%1,%2,%3}, [%4];"
                 : "=r"(r0), "=r"(r1), "=r"(r2), "=r"(r3) : "r"(addr));
}

__device__ __forceinline__ void ldmatrix_x2(
    uint32_t& r0, uint32_t& r1, uint32_t addr)
{
    asm volatile("ldmatrix.sync.aligned.m8n8.x2.shared.b16 {%0,%1}, [%2];"
                 : "=r"(r0), "=r"(r1) : "r"(addr));
}

__device__ __forceinline__ void mma_bf16(
    float* c, const uint32_t* a, const uint32_t* b)
{
    asm volatile(
        "mma.sync.aligned.m16n8k16.row.col.f32.bf16.bf16.f32 "
        "{%0,%1,%2,%3}, {%4,%5,%6,%7}, {%8,%9}, {%0,%1,%2,%3};"
        : "+f"(c[0]), "+f"(c[1]), "+f"(c[2]), "+f"(c[3])
        : "r"(a[0]), "r"(a[1]), "r"(a[2]), "r"(a[3]), "r"(b[0]), "r"(b[1]));
}

// ---------------------------------------------------------------------------
// bf16 split helpers
// ---------------------------------------------------------------------------
__device__ __forceinline__ void split_store4(
    float4 v, __nv_bfloat16* hi, __nv_bfloat16* lo, size_t idx)
{
    __nv_bfloat16 h0 = __float2bfloat16(v.x);
    __nv_bfloat16 h1 = __float2bfloat16(v.y);
    __nv_bfloat16 h2 = __float2bfloat16(v.z);
    __nv_bfloat16 h3 = __float2bfloat16(v.w);
    __nv_bfloat16 l0 = __float2bfloat16(v.x - __bfloat162float(h0));
    __nv_bfloat16 l1 = __float2bfloat16(v.y - __bfloat162float(h1));
    __nv_bfloat16 l2 = __float2bfloat16(v.z - __bfloat162float(h2));
    __nv_bfloat16 l3 = __float2bfloat16(v.w - __bfloat162float(h3));
    __nv_bfloat162* ph = reinterpret_cast<__nv_bfloat162*>(hi + idx);
    __nv_bfloat162* pl = reinterpret_cast<__nv_bfloat162*>(lo + idx);
    ph[0] = __halves2bfloat162(h0, h1);
    ph[1] = __halves2bfloat162(h2, h3);
    pl[0] = __halves2bfloat162(l0, l1);
    pl[1] = __halves2bfloat162(l2, l3);
}

__device__ __forceinline__ void split_store2(
    float a, float b, __nv_bfloat16* hi, __nv_bfloat16* lo, size_t idx)
{
    __nv_bfloat16 h0 = __float2bfloat16(a);
    __nv_bfloat16 h1 = __float2bfloat16(b);
    __nv_bfloat16 l0 = __float2bfloat16(a - __bfloat162float(h0));
    __nv_bfloat16 l1 = __float2bfloat16(b - __bfloat162float(h1));
    *reinterpret_cast<__nv_bfloat162*>(hi + idx) = __halves2bfloat162(h0, h1);
    *reinterpret_cast<__nv_bfloat162*>(lo + idx) = __halves2bfloat162(l0, l1);
}

// ---------------------------------------------------------------------------
// LayerNorm -> split bf16 (hi/lo). One block per row, 256 threads.
// ---------------------------------------------------------------------------
__device__ __forceinline__ void ln_body(
    const float* __restrict__ in, const float* __restrict__ gam,
    const float* __restrict__ bet, __nv_bfloat16* __restrict__ oh,
    __nv_bfloat16* __restrict__ ol)
{
    int row = blockIdx.x;
    int t   = threadIdx.x;
    const float4* rin = reinterpret_cast<const float4*>(in + (size_t)row * CDIM);
    float4 v = rin[t];
    float s  = v.x + v.y + v.z + v.w;
    float sq = v.x * v.x + v.y * v.y + v.z * v.z + v.w * v.w;
    #pragma unroll
    for (int o = 16; o; o >>= 1) {
        s  += __shfl_xor_sync(0xffffffffu, s,  o);
        sq += __shfl_xor_sync(0xffffffffu, sq, o);
    }
    __shared__ float ss[8], ssq[8];
    int w = t >> 5, l = t & 31;
    if (l == 0) { ss[w] = s; ssq[w] = sq; }
    __syncthreads();
    if (w == 0) {
        s  = (l < 8) ? ss[l]  : 0.0f;
        sq = (l < 8) ? ssq[l] : 0.0f;
        #pragma unroll
        for (int o = 4; o; o >>= 1) {
            s  += __shfl_xor_sync(0xffffffffu, s,  o);
            sq += __shfl_xor_sync(0xffffffffu, sq, o);
        }
        if (l == 0) { ss[0] = s; ssq[0] = sq; }
    }
    __syncthreads();
    float mu  = ss[0] * (1.0f / CDIM);
    float var = ssq[0] * (1.0f / CDIM) - mu * mu;
    float rs  = rsqrtf(var + 1e-5f);
    float4 gv = reinterpret_cast<const float4*>(gam)[t];
    float4 bv = reinterpret_cast<const float4*>(bet)[t];
    float4 o4;
    o4.x = (v.x - mu) * rs * gv.x + bv.x;
    o4.y = (v.y - mu) * rs * gv.y + bv.y;
    o4.z = (v.z - mu) * rs * gv.z + bv.z;
    o4.w = (v.w - mu) * rs * gv.w + bv.w;
    split_store4(o4, oh, ol, (size_t)row * CDIM + t * 4);
}

__global__ __launch_bounds__(256) void ln1_kernel(
    const float* __restrict__ x, const float* __restrict__ gam,
    const float* __restrict__ bet)
{
    ln_body(x, gam, bet, g_ah1, g_al1);
}

__global__ __launch_bounds__(256) void ln2_kernel(
    const float* __restrict__ gam, const float* __restrict__ bet)
{
    ln_body(g_x2, gam, bet, g_ah1, g_al1);
}

// ---------------------------------------------------------------------------
// Tensor-core GEMM via mma.sync bf16 (3-pass precision split).
// D[M,N] = (Ah+Al)[M,K] @ (Bh+Bl)[N,K]^T   (B pre-transposed, K-major)
// CTA tile 128x128, 256 threads (8 warps), warp tile 32x64.
// SMEM rows: 128 bytes = 32 bf16 hi | 32 bf16 lo per K-chunk of 32 fp32.
// SW128 swizzle for conflict-free ldmatrix. Software prefetch of next chunk.
// MODE 0: +bias -> Cf.  MODE 1: relu(+bias) -> split Chi/Clo.  MODE 2: +bias+res -> Cf.
// ---------------------------------------------------------------------------
#define SWZ(o) ((o) ^ (((o) >> 3) & 0x70))

template <int MODE>
__device__ __forceinline__ void mma_gemm_body(
    const __nv_bfloat16* __restrict__ Ah, const __nv_bfloat16* __restrict__ Al,
    const __nv_bfloat16* __restrict__ Bh, const __nv_bfloat16* __restrict__ Bl,
    const float* __restrict__ bias, const float* __restrict__ res,
    float* __restrict__ Cf, __nv_bfloat16* __restrict__ Chi,
    __nv_bfloat16* __restrict__ Clo, int M, int N, int K)
{
    __shared__ __align__(128) char smA[128 * 128];  // 16 KB
    __shared__ __align__(128) char smB[128 * 128];  // 16 KB

    int tid  = threadIdx.x;
    int lane = tid & 31, wid = tid >> 5;
    int bm = blockIdx.y * 128;
    int bn = blockIdx.x * 128;

    uint32_t sa = smem_u32(smA);   // shared-space addr, for ldmatrix only
    uint32_t sb = smem_u32(smB);

    // ---- staging mapping: row = tid>>1 (0..127), half = tid&1 (hi/lo) ----
    int srow = tid >> 1;
    int shalf = tid & 1;
    const char* gA = (const char*)((shalf ? Al : Ah) + (size_t)(bm + srow) * K);
    const char* gB = (const char*)((shalf ? Bl : Bh) + (size_t)(bn + srow) * K);
    uint32_t offS[4];              // swizzled BYTE offsets (used with C++ ptrs)
    #pragma unroll
    for (int u = 0; u < 4; ++u)
        offS[u] = SWZ((uint32_t)(srow * 128 + (shalf * 4 + u) * 16));

    // ---- warp tile: m0 = (wid&3)*32, n0 = (wid>>2)*64 ----
    int m0 = (wid & 3) * 32;
    int n0 = (wid >> 2) * 64;

    // ldmatrix address precompute (shared-space addresses)
    uint32_t aBase[2], aMask[2];
    #pragma unroll
    for (int mf = 0; mf < 2; ++mf) {
        int r = m0 + mf * 16 + (lane & 15);
        aBase[mf] = sa + r * 128;
        aMask[mf] = (r & 7) * 16;
    }
    uint32_t kh16A = (lane >> 4) * 16;
    uint32_t bBase[8], bMask[8];
    #pragma unroll
    for (int nf = 0; nf < 8; ++nf) {
        int r = n0 + nf * 8 + (lane & 7);
        bBase[nf] = sb + r * 128;
        bMask[nf] = (r & 7) * 16;
    }
    uint32_t kh16B = ((lane >> 3) & 1) * 16;

    float acc[2][8][4];
    #pragma unroll
    for (int mf = 0; mf < 2; ++mf)
        #pragma unroll
        for (int nf = 0; nf < 8; ++nf)
            #pragma unroll
            for (int e = 0; e < 4; ++e) acc[mf][nf][e] = 0.0f;

    const int nk = K >> 5;   // chunks of 32 fp32 (64 bytes hi | 64 bytes lo)

    // prologue: stage chunk 0
    uint4 ra[4], rb[4];
    #pragma unroll
    for (int u = 0; u < 4; ++u) {
        ra[u] = *(const uint4*)(gA + u * 16);
        rb[u] = *(const uint4*)(gB + u * 16);
    }

    for (int kc = 0; kc < nk; ++kc) {
        __syncthreads();   // previous compute finished; smem reusable
        #pragma unroll
        for (int u = 0; u < 4; ++u) {
            *reinterpret_cast<uint4*>(smA + offS[u]) = ra[u];
            *reinterpret_cast<uint4*>(smB + offS[u]) = rb[u];
        }
        __syncthreads();

        // prefetch next chunk (overlaps with mma below)
        if (kc + 1 < nk) {
            const char* pA = gA + (size_t)(kc + 1) * 64;
            const char* pB = gB + (size_t)(kc + 1) * 64;
            #pragma unroll
            for (int u = 0; u < 4; ++u) {
                ra[u] = *(const uint4*)(pA + u * 16);
                rb[u] = *(const uint4*)(pB + u * 16);
            }
        }

        #pragma unroll
        for (int k16 = 0; k16 < 2; ++k16) {
            uint32_t c_hi = k16 * 32;        // hi bytes 0..63
            uint32_t c_lo = 64 + k16 * 32;   // lo bytes 64..127

            uint32_t ah[2][4], al[2][4];
            #pragma unroll
            for (int mf = 0; mf < 2; ++mf) {
                ldmatrix_x4(ah[mf][0], ah[mf][1], ah[mf][2], ah[mf][3],
                            aBase[mf] + ((c_hi + kh16A) ^ aMask[mf]));
                ldmatrix_x4(al[mf][0], al[mf][1], al[mf][2], al[mf][3],
                            aBase[mf] + ((c_lo + kh16A) ^ aMask[mf]));
            }
            // B hi: passes hh (Ah*Bh) and lh (Al*Bh)
            #pragma unroll
            for (int nf = 0; nf < 8; ++nf) {
                uint32_t bh[2];
                ldmatrix_x2(bh[0], bh[1],
                            bBase[nf] + ((c_hi + kh16B) ^ bMask[nf]));
                #pragma unroll
                for (int mf = 0; mf < 2; ++mf) {
                    mma_bf16(acc[mf][nf], ah[mf], bh);
                    mma_bf16(acc[mf][nf], al[mf], bh);
                }
            }
            // B lo: pass hl (Ah*Bl)
            #pragma unroll
            for (int nf = 0; nf < 8; ++nf) {
                uint32_t bl[2];
                ldmatrix_x2(bl[0], bl[1],
                            bBase[nf] + ((c_lo + kh16B) ^ bMask[nf]));
                #pragma unroll
                for (int mf = 0; mf < 2; ++mf)
                    mma_bf16(acc[mf][nf], ah[mf], bl);
            }
        }
    }

    // ---- epilogue ----
    int rql = lane >> 2;          // 0..7
    int cql = (lane & 3) * 2;     // 0,2,..6
    #pragma unroll
    for (int mf = 0; mf < 2; ++mf) {
        #pragma unroll
        for (int nf = 0; nf < 8; ++nf) {
            int gn = bn + n0 + nf * 8 + cql;
            float bx = bias[gn], by = bias[gn + 1];
            #pragma unroll
            for (int half = 0; half < 2; ++half) {
                int gm = bm + m0 + mf * 16 + rql + half * 8;
                float v0 = acc[mf][nf][half * 2 + 0] + bx;
                float v1 = acc[mf][nf][half * 2 + 1] + by;
                size_t oi = (size_t)gm * N + gn;
                if (MODE == 1) {
                    v0 = fmaxf(v0, 0.0f);
                    v1 = fmaxf(v1, 0.0f);
                    split_store2(v0, v1, Chi, Clo, oi);
                } else {
                    if (MODE == 2) {
                        float2 rv = *reinterpret_cast<const float2*>(res + oi);
                        v0 += rv.x; v1 += rv.y;
                    }
                    float2 o2 = {v0, v1};
                    *reinterpret_cast<float2*>(Cf + oi) = o2;
                }
            }
        }
    }
}

__global__ __launch_bounds__(256) void gemm_qkv_kernel(const float* __restrict__ b)
{
    mma_gemm_body<0>(g_ah1, g_al1, g_wqh, g_wql, b, nullptr,
                     g_qkv, nullptr, nullptr, MDIM, C3, CDIM);
}

__global__ __launch_bounds__(256) void gemm_mlp1_kernel(const float* __restrict__ b)
{
    mma_gemm_body<1>(g_ah1, g_al1, g_w1h, g_w1l, b, nullptr,
                     nullptr, g_ah2, g_al2, MDIM, H4DIM, CDIM);
}

__global__ __launch_bounds__(256) void gemm_mlp2_kernel(
    const float* __restrict__ b, float* __restrict__ out)
{
    mma_gemm_body<2>(g_ah2, g_al2, g_w2h, g_w2l, b, g_x2,
                     out, nullptr, nullptr, MDIM, CDIM, H4DIM);
}

// ---------------------------------------------------------------------------
// Flash attention, fp32, static smem (<48KB). Unchanged from R2 (passing).
// ---------------------------------------------------------------------------
#define KT 32       // key tile
#define SP 33       // score pitch

__global__ __launch_bounds__(256) void attn_kernel(const float* __restrict__ xin)
{
    __shared__ float Qt[64 * 64];
    __shared__ float Kt[64 * KT];
    __shared__ float Vs[KT * 64];
    __shared__ float Ss[64 * SP];
    __shared__ float row_m[64], row_l[64], row_a[64];

    const float SCALE = 1.0f / 32.0f;  // 1/sqrt(C) per source

    int tid  = threadIdx.x;
    int tx   = tid & 15, ty = tid >> 4;
    int lane = tid & 31, warp = tid >> 5;

    int bh = blockIdx.y;
    int b  = bh >> 4;
    int h  = bh & 15;
    int qbase = blockIdx.x * 64;

    const float* qkv_b = g_qkv + (size_t)b * NSEQ * C3;

    int tm  = tid >> 2;
    int tdg = (tid & 3) << 4;
    {
        const float* qp = qkv_b + (size_t)(qbase + tm) * C3 + h * HD + tdg;
        #pragma unroll
        for (int i = 0; i < 4; ++i) {
            float4 v = *reinterpret_cast<const float4*>(qp + 4 * i);
            int d = tdg + 4 * i;
            Qt[(d + 0) * 64 + tm] = v.x;
            Qt[(d + 1) * 64 + tm] = v.y;
            Qt[(d + 2) * 64 + tm] = v.z;
            Qt[(d + 3) * 64 + tm] = v.w;
        }
    }
    if (tid < 64) { row_m[tid] = -1e30f; row_l[tid] = 0.0f; }

    float o_acc[4][4];
    #pragma unroll
    for (int i = 0; i < 4; ++i)
        #pragma unroll
        for (int j = 0; j < 4; ++j) o_acc[i][j] = 0.0f;

    int km  = tid >> 3;
    int kdg = (tid & 7) << 3;

    for (int kt = 0; kt < NSEQ / KT; ++kt) {
        int kbase = kt * KT;
        {
            const float* kp = qkv_b + (size_t)(kbase + km) * C3 + CDIM + h * HD + kdg;
            #pragma unroll
            for (int i = 0; i < 2; ++i) {
                float4 v = *reinterpret_cast<const float4*>(kp + 4 * i);
                int d = kdg + 4 * i;
                Kt[(d + 0) * KT + km] = v.x;
                Kt[(d + 1) * KT + km] = v.y;
                Kt[(d + 2) * KT + km] = v.z;
                Kt[(d + 3) * KT + km] = v.w;
            }
            const float* vp = qkv_b + (size_t)(kbase + km) * C3 + 2 * CDIM + h * HD + kdg;
            #pragma unroll
            for (int i = 0; i < 2; ++i)
                *reinterpret_cast<float4*>(&Vs[km * 64 + kdg + 4 * i]) =
                    *reinterpret_cast<const float4*>(vp + 4 * i);
        }
        __syncthreads();

        float s_acc[4][2];
        #pragma unroll
        for (int i = 0; i < 4; ++i) { s_acc[i][0] = 0.0f; s_acc[i][1] = 0.0f; }
        for (int d = 0; d < 64; ++d) {
            float4 qa = *reinterpret_cast<float4*>(&Qt[d * 64 + ty * 4]);
            float2 kb = *reinterpret_cast<float2*>(&Kt[d * KT + tx * 2]);
            float aq[4] = {qa.x, qa.y, qa.z, qa.w};
            #pragma unroll
            for (int i = 0; i < 4; ++i) {
                s_acc[i][0] = fmaf(aq[i], kb.x, s_acc[i][0]);
                s_acc[i][1] = fmaf(aq[i], kb.y, s_acc[i][1]);
            }
        }
        #pragma unroll
        for (int i = 0; i < 4; ++i) {
            Ss[(ty * 4 + i) * SP + tx * 2 + 0] = s_acc[i][0] * SCALE;
            Ss[(ty * 4 + i) * SP + tx * 2 + 1] = s_acc[i][1] * SCALE;
        }
        __syncthreads();

        #pragma unroll
        for (int r = 0; r < 8; ++r) {
            int m = warp * 8 + r;
            float s1 = Ss[m * SP + lane];
            float mx = s1;
            #pragma unroll
            for (int o = 16; o; o >>= 1)
                mx = fmaxf(mx, __shfl_xor_sync(0xffffffffu, mx, o));
            float mold = row_m[m];
            float mnew = fmaxf(mold, mx);
            float p1 = __expf(s1 - mnew);
            float ps = p1;
            #pragma unroll
            for (int o = 16; o; o >>= 1)
                ps += __shfl_xor_sync(0xffffffffu, ps, o);
            if (lane == 0) {
                float alpha = __expf(mold - mnew);
                row_a[m] = alpha;
                row_l[m] = row_l[m] * alpha + ps;
                row_m[m] = mnew;
            }
            Ss[m * SP + lane] = p1;
        }
        __syncthreads();

        float al[4];
        #pragma unroll
        for (int i = 0; i < 4; ++i) al[i] = row_a[ty * 4 + i];
        #pragma unroll
        for (int i = 0; i < 4; ++i)
            #pragma unroll
            for (int j = 0; j < 4; ++j) o_acc[i][j] *= al[i];
        #pragma unroll 4
        for (int j = 0; j < KT; ++j) {
            float4 vb = *reinterpret_cast<float4*>(&Vs[j * 64 + tx * 4]);
            float pv[4];
            #pragma unroll
            for (int i = 0; i < 4; ++i) pv[i] = Ss[(ty * 4 + i) * SP + j];
            #pragma unroll
            for (int i = 0; i < 4; ++i) {
                o_acc[i][0] = fmaf(pv[i], vb.x, o_acc[i][0]);
                o_acc[i][1] = fmaf(pv[i], vb.y, o_acc[i][1]);
                o_acc[i][2] = fmaf(pv[i], vb.z, o_acc[i][2]);
                o_acc[i][3] = fmaf(pv[i], vb.w, o_acc[i][3]);
            }
        }
        __syncthreads();
    }

    #pragma unroll
    for (int i = 0; i < 4; ++i) {
        int m = ty * 4 + i;
        int n = qbase + m;
        float invl = 1.0f / row_l[m];
        int np = h * 128 + (n >> 4);
        int cbase = (n & 15) << 6;
        #pragma unroll
        for (int j = 0; j < 4; ++j) {
            int d = tx * 4 + j;
            size_t oi = ((size_t)b * NSEQ + np) * CDIM + cbase + d;
            g_x2[oi] = xin[oi] + o_acc[i][j] * invl;
        }
    }
}

// ---------------------------------------------------------------------------
// Weight transpose + bf16 split wrappers
// ---------------------------------------------------------------------------
__global__ __launch_bounds__(256) void tr_qkv_kernel(const float* __restrict__ w)
{
    __shared__ float t[32][33];
    int bx = blockIdx.x * 32, by = blockIdx.y * 32;
    int tx = threadIdx.x, ty = threadIdx.y;
    #pragma unroll
    for (int i = 0; i < 4; ++i)
        t[ty + i * 8][tx] = w[(size_t)(by + ty + i * 8) * C3 + bx + tx];
    __syncthreads();
    #pragma unroll
    for (int i = 0; i < 4; ++i) {
        float v = t[tx][ty + i * 8];
        __nv_bfloat16 h = __float2bfloat16(v);
        size_t oi = (size_t)(bx + ty + i * 8) * CDIM + by + tx;
        g_wqh[oi] = h;
        g_wql[oi] = __float2bfloat16(v - __bfloat162float(h));
    }
}

__global__ __launch_bounds__(256) void tr_w1_kernel(const float* __restrict__ w)
{
    __shared__ float t[32][33];
    int bx = blockIdx.x * 32, by = blockIdx.y * 32;
    int tx = threadIdx.x, ty = threadIdx.y;
    #pragma unroll
    for (int i = 0; i < 4; ++i)
        t[ty + i * 8][tx] = w[(size_t)(by + ty + i * 8) * H4DIM + bx + tx];
    __syncthreads();
    #pragma unroll
    for (int i = 0; i < 4; ++i) {
        float v = t[tx][ty + i * 8];
        __nv_bfloat16 h = __float2bfloat16(v);
        size_t oi = (size_t)(bx + ty + i * 8) * CDIM + by + tx;
        g_w1h[oi] = h;
        g_w1l[oi] = __float2bfloat16(v - __bfloat162float(h));
    }
}

__global__ __launch_bounds__(256) void tr_w2_kernel(const float* __restrict__ w)
{
    __shared__ float t[32][33];
    int bx = blockIdx.x * 32, by = blockIdx.y * 32;
    int tx = threadIdx.x, ty = threadIdx.y;
    #pragma unroll
    for (int i = 0; i < 4; ++i)
        t[ty + i * 8][tx] = w[(size_t)(by + ty + i * 8) * CDIM + bx + tx];
    __syncthreads();
    #pragma unroll
    for (int i = 0; i < 4; ++i) {
        float v = t[tx][ty + i * 8];
        __nv_bfloat16 h = __float2bfloat16(v);
        size_t oi = (size_t)(bx + ty + i * 8) * H4DIM + by + tx;
        g_w2h[oi] = h;
        g_w2l[oi] = __float2bfloat16(v - __bfloat162float(h));
    }
}

// ---------------------------------------------------------------------------
// Launch: kernel launches only (graph-capturable)
// ---------------------------------------------------------------------------
extern "C" void kernel_launch(void* const* d_in, const int* in_sizes, int n_in,
                              void* d_out, int out_size)
{
    const float* x     = (const float*)d_in[0];
    const float* qkv_w = (const float*)d_in[1];
    const float* qkv_b = (const float*)d_in[2];
    const float* w1    = (const float*)d_in[3];
    const float* b1    = (const float*)d_in[4];
    const float* w2    = (const float*)d_in[5];
    const float* b2    = (const float*)d_in[6];
    const float* ln1_g = (const float*)d_in[7];
    const float* ln1_b = (const float*)d_in[8];
    const float* ln2_g = (const float*)d_in[9];
    const float* ln2_b = (const float*)d_in[10];
    float* out = (float*)d_out;

    dim3 tb(32, 8);
    tr_qkv_kernel<<<dim3(C3 / 32, CDIM / 32), tb>>>(qkv_w);
    tr_w1_kernel <<<dim3(H4DIM / 32, CDIM / 32), tb>>>(w1);
    tr_w2_kernel <<<dim3(CDIM / 32, H4DIM / 32), tb>>>(w2);

    // 1. LN1: x -> (g_ah1, g_al1)
    ln1_kernel<<<MDIM, 256>>>(x, ln1_g, ln1_b);
    // 2. QKV projection (mma.sync bf16x2): -> g_qkv fp32
    gemm_qkv_kernel<<<dim3(C3 / 128, MDIM / 128), 256>>>(qkv_b);
    // 3. Attention (+ interleaved reshape + residual): -> g_x2
    attn_kernel<<<dim3(NSEQ / 64, BDIM * NHEAD), 256>>>(x);
    // 4. LN2: g_x2 -> (g_ah1, g_al1)
    ln2_kernel<<<MDIM, 256>>>(ln2_g, ln2_b);
    // 5. MLP up + relu (mma.sync bf16x2): -> (g_ah2, g_al2)
    gemm_mlp1_kernel<<<dim3(H4DIM / 128, MDIM / 128), 256>>>(b1);
    // 6. MLP down + bias + residual (mma.sync bf16x2): -> out
    gemm_mlp2_kernel<<<dim3(CDIM / 128, MDIM / 128), 256>>>(b2, out);
}